// round 1
// baseline (speedup 1.0000x reference)
#include <cuda_runtime.h>

// Problem: B=8192, D=512, U=512, M=16, K=64
//   keyv = x @ key_kernel + key_bias          [B,64]
//   sim  = 1/(||keyv - keys_map||_2 + 1)      [B,16]
//   out  = einsum(bm,bd,mdu->bu)(sim,x,kernels)/M + (sim@biases)/M
//
// Fused as ONE GEMM: C[B,U] = A'[B, M*D+M] @ W[M*D+M, U]
//   A'[b, m*512+d] = sim[b,m]*x[b,d]   (generated on the fly)
//   A'[b, 8192+m]  = sim[b,m]          (bias fold-in, one extra K-chunk)
//   W rows 0..8191 = kernels flat [M*D, U] (natural layout)
//   W rows 8192+m  = biases[m,:]
// Final scale 1/16.
//
// fp32 SIMT GEMM using packed fma.rn.f32x2 (2x the FFMA rate on sm_103a).

#define B_SZ 8192
#define D_SZ 512
#define U_SZ 512
#define M_SZ 16
#define K_SZ 64

#define BM 128
#define BN 128
#define BK 16
#define AST 132   // padded A-tile stride (16B-aligned, reduces STS conflicts)

__device__ float g_sim[B_SZ * M_SZ];

typedef unsigned long long ull;

__device__ __forceinline__ ull pk2(float a, float b) {
    ull r;
    asm("mov.b64 %0, {%1, %2};" : "=l"(r) : "f"(a), "f"(b));
    return r;
}
__device__ __forceinline__ void fma2(ull& d, ull a, ull b) {
    asm("fma.rn.f32x2 %0, %1, %2, %0;" : "+l"(d) : "l"(a), "l"(b));
}
__device__ __forceinline__ float2 upk2(ull v) {
    float2 r;
    asm("mov.b64 {%0, %1}, %2;" : "=f"(r.x), "=f"(r.y) : "l"(v));
    return r;
}

// ---------------------------------------------------------------------------
// Kernel 1: keyv = x @ key_kernel + key_bias ; sim = 1/(dist+1) -> g_sim
// One block = 16 rows of x. 128 threads.
// ---------------------------------------------------------------------------
__global__ __launch_bounds__(128) void sim_kernel(
    const float* __restrict__ x,
    const float* __restrict__ key_kernel,
    const float* __restrict__ key_bias,
    const float* __restrict__ keys_map)
{
    __shared__ float xs[16 * D_SZ];   // 32 KB
    __shared__ float kv[16][K_SZ];    // 4 KB

    int tid = threadIdx.x;
    int b0 = blockIdx.x * 16;

    for (int i = tid; i < 16 * D_SZ; i += 128)
        xs[i] = x[b0 * D_SZ + i];
    __syncthreads();

    // keyv: thread handles one k, 8 rows (stride 2)
    int k = tid & 63;
    int rg = tid >> 6;  // 0..1
    float acc[8];
#pragma unroll
    for (int r = 0; r < 8; r++) acc[r] = 0.f;
    for (int d = 0; d < D_SZ; d++) {
        float kkv = key_kernel[d * K_SZ + k];
#pragma unroll
        for (int r = 0; r < 8; r++)
            acc[r] += xs[(rg + 2 * r) * D_SZ + d] * kkv;
    }
    float kb = key_bias[k];
#pragma unroll
    for (int r = 0; r < 8; r++)
        kv[rg + 2 * r][k] = acc[r] + kb;
    __syncthreads();

    // sim: 16 rows x 16 modes = 256 outputs, 2 per thread
    int r = tid >> 3;   // 0..15
    int m0 = tid & 7;
#pragma unroll
    for (int h = 0; h < 2; h++) {
        int m = m0 + h * 8;
        float d2 = 0.f;
#pragma unroll 8
        for (int kk = 0; kk < K_SZ; kk++) {
            float diff = kv[r][kk] - keys_map[m * K_SZ + kk];
            d2 += diff * diff;
        }
        g_sim[(b0 + r) * M_SZ + m] = 1.0f / (sqrtf(d2) + 1.0f);
    }
}

// ---------------------------------------------------------------------------
// Kernel 2: fused GEMM. 128x128 tile, BK=16, 256 threads, 8x8 microtile
// (split 4+4 rows/cols for conflict-free float4 smem fragments).
// K-loop: 512 chunks over (m,d) + 1 bias chunk = 513.
// ---------------------------------------------------------------------------
__global__ __launch_bounds__(256, 2) void pd_gemm(
    const float* __restrict__ x,
    const float* __restrict__ kernels,
    const float* __restrict__ biases,
    float* __restrict__ out)
{
    __shared__ float As[2][BK][AST];       // 16.5 KB
    __shared__ float Bs[2][BK][BN];        // 16 KB
    __shared__ float Ss[BM][M_SZ];         // 8 KB

    int tid = threadIdx.x;
    int tx = tid & 15;
    int ty = tid >> 4;
    int brow0 = blockIdx.y * BM;
    int bcol0 = blockIdx.x * BN;

    // cache sim for this row-block
    for (int i = tid; i < BM * M_SZ; i += 256)
        (&Ss[0][0])[i] = g_sim[brow0 * M_SZ + i];
    __syncthreads();

    float4 aR[2], bR[2];

    const int NK = 513;

    auto loadRegs = [&](int kt) {
        int m = kt >> 5;           // mode for this chunk (kt<512)
        int d0 = (kt & 31) << 4;   // d offset within mode
#pragma unroll
        for (int v = 0; v < 2; v++) {
            int lin = tid + v * 256;
            int row = lin >> 2;
            int kf4 = lin & 3;
            if (kt < 512) {
                const float4 xv = *reinterpret_cast<const float4*>(
                    &x[(brow0 + row) * D_SZ + d0 + kf4 * 4]);
                float s = Ss[row][m];
                aR[v] = make_float4(xv.x * s, xv.y * s, xv.z * s, xv.w * s);
            } else {
                aR[v] = make_float4(Ss[row][kf4 * 4 + 0], Ss[row][kf4 * 4 + 1],
                                    Ss[row][kf4 * 4 + 2], Ss[row][kf4 * 4 + 3]);
            }
            int krow = lin >> 5;
            int cf4 = lin & 31;
            const float* src = (kt < 512)
                ? &kernels[(kt * BK + krow) * U_SZ + bcol0 + cf4 * 4]
                : &biases[krow * U_SZ + bcol0 + cf4 * 4];
            bR[v] = *reinterpret_cast<const float4*>(src);
        }
    };

    auto storeRegs = [&](int buf) {
#pragma unroll
        for (int v = 0; v < 2; v++) {
            int lin = tid + v * 256;
            int row = lin >> 2;
            int kf4 = lin & 3;
            As[buf][kf4 * 4 + 0][row] = aR[v].x;
            As[buf][kf4 * 4 + 1][row] = aR[v].y;
            As[buf][kf4 * 4 + 2][row] = aR[v].z;
            As[buf][kf4 * 4 + 3][row] = aR[v].w;
            int krow = lin >> 5;
            int cf4 = lin & 31;
            *reinterpret_cast<float4*>(&Bs[buf][krow][cf4 * 4]) = bR[v];
        }
    };

    ull acc[8][4];
#pragma unroll
    for (int i = 0; i < 8; i++)
#pragma unroll
        for (int j = 0; j < 4; j++) acc[i][j] = pk2(0.f, 0.f);

    loadRegs(0);
    storeRegs(0);
    __syncthreads();

    for (int kt = 0; kt < NK; kt++) {
        int buf = kt & 1;
        if (kt + 1 < NK) loadRegs(kt + 1);
#pragma unroll
        for (int kk = 0; kk < BK; kk++) {
            float4 a0 = *reinterpret_cast<const float4*>(&As[buf][kk][ty * 4]);
            float4 a1 = *reinterpret_cast<const float4*>(&As[buf][kk][64 + ty * 4]);
            float4 b0 = *reinterpret_cast<const float4*>(&Bs[buf][kk][tx * 4]);
            float4 b1 = *reinterpret_cast<const float4*>(&Bs[buf][kk][64 + tx * 4]);
            ull b2[4] = { pk2(b0.x, b0.y), pk2(b0.z, b0.w),
                          pk2(b1.x, b1.y), pk2(b1.z, b1.w) };
            float av[8] = { a0.x, a0.y, a0.z, a0.w, a1.x, a1.y, a1.z, a1.w };
#pragma unroll
            for (int i = 0; i < 8; i++) {
                ull a2 = pk2(av[i], av[i]);
#pragma unroll
                for (int j = 0; j < 4; j++) fma2(acc[i][j], a2, b2[j]);
            }
        }
        if (kt + 1 < NK) storeRegs((kt + 1) & 1);
        __syncthreads();
    }

    const float sc = 1.0f / 16.0f;
#pragma unroll
    for (int i = 0; i < 8; i++) {
        int row = brow0 + ((i < 4) ? (ty * 4 + i) : (64 + ty * 4 + (i - 4)));
        float2 p0 = upk2(acc[i][0]);
        float2 p1 = upk2(acc[i][1]);
        float2 p2 = upk2(acc[i][2]);
        float2 p3 = upk2(acc[i][3]);
        float4 o0 = make_float4(p0.x * sc, p0.y * sc, p1.x * sc, p1.y * sc);
        float4 o1 = make_float4(p2.x * sc, p2.y * sc, p3.x * sc, p3.y * sc);
        *reinterpret_cast<float4*>(&out[row * U_SZ + bcol0 + tx * 4]) = o0;
        *reinterpret_cast<float4*>(&out[row * U_SZ + bcol0 + 64 + tx * 4]) = o1;
    }
}

// ---------------------------------------------------------------------------
extern "C" void kernel_launch(void* const* d_in, const int* in_sizes, int n_in,
                              void* d_out, int out_size)
{
    const float* x          = (const float*)d_in[0];
    const float* key_kernel = (const float*)d_in[1];
    const float* key_bias   = (const float*)d_in[2];
    const float* keys_map   = (const float*)d_in[3];
    const float* kernels    = (const float*)d_in[4];
    const float* biases     = (const float*)d_in[5];
    float* out = (float*)d_out;

    sim_kernel<<<B_SZ / 16, 128>>>(x, key_kernel, key_bias, keys_map);

    dim3 grid(U_SZ / BN, B_SZ / BM);
    pd_gemm<<<grid, 256>>>(x, kernels, biases, out);
}

// round 3
// speedup vs baseline: 1.9007x; 1.9007x over previous
#include <cuda_runtime.h>
#include <cuda_bf16.h>
#include <cstdint>

#define B_SZ 8192
#define D_SZ 512
#define U_SZ 512
#define M_SZ 16

// ---------------------------------------------------------------------------
// Scratch (static __device__ — no allocations allowed)
// ---------------------------------------------------------------------------
__device__ float         g_sim[B_SZ * M_SZ];          // sim/16
__device__ __nv_bfloat16 g_xhi[B_SZ * D_SZ];
__device__ __nv_bfloat16 g_xlo[B_SZ * D_SZ];
__device__ __nv_bfloat16 g_whi[M_SZ * U_SZ * D_SZ];   // [m][u][d]  (k-major B)
__device__ __nv_bfloat16 g_wlo[M_SZ * U_SZ * D_SZ];

// ---------------------------------------------------------------------------
// helpers
// ---------------------------------------------------------------------------
__device__ __forceinline__ uint32_t smem_u32(const void* p) {
    uint32_t a;
    asm("{ .reg .u64 t; cvta.to.shared.u64 t, %1; cvt.u32.u64 %0, t; }"
        : "=r"(a) : "l"(p));
    return a;
}
__device__ __forceinline__ void cp_async16(uint32_t saddr, const void* gaddr) {
    asm volatile("cp.async.cg.shared.global [%0], [%1], 16;"
                 :: "r"(saddr), "l"(gaddr) : "memory");
}
__device__ __forceinline__ void ldsm4(uint32_t* r, uint32_t a) {
    asm volatile("ldmatrix.sync.aligned.m8n8.x4.shared.b16 {%0,%1,%2,%3}, [%4];"
                 : "=r"(r[0]), "=r"(r[1]), "=r"(r[2]), "=r"(r[3]) : "r"(a));
}
__device__ __forceinline__ void ldsm2(uint32_t* r, uint32_t a) {
    asm volatile("ldmatrix.sync.aligned.m8n8.x2.shared.b16 {%0,%1}, [%2];"
                 : "=r"(r[0]), "=r"(r[1]) : "r"(a));
}
__device__ __forceinline__ void mma16816(float* c, const uint32_t* a, const uint32_t* b) {
    asm volatile(
        "mma.sync.aligned.m16n8k16.row.col.f32.bf16.bf16.f32 "
        "{%0,%1,%2,%3}, {%4,%5,%6,%7}, {%8,%9}, {%0,%1,%2,%3};"
        : "+f"(c[0]), "+f"(c[1]), "+f"(c[2]), "+f"(c[3])
        : "r"(a[0]), "r"(a[1]), "r"(a[2]), "r"(a[3]), "r"(b[0]), "r"(b[1]));
}

// ---------------------------------------------------------------------------
// Prep: fp32 -> bf16 hi/lo split of x
// ---------------------------------------------------------------------------
__global__ __launch_bounds__(256) void conv_x(const float* __restrict__ x) {
    size_t i = ((size_t)blockIdx.x * 256 + threadIdx.x) * 4;
    float4 v = *reinterpret_cast<const float4*>(x + i);
    __nv_bfloat16 h0 = __float2bfloat16_rn(v.x), h1 = __float2bfloat16_rn(v.y);
    __nv_bfloat16 h2 = __float2bfloat16_rn(v.z), h3 = __float2bfloat16_rn(v.w);
    __nv_bfloat16 l0 = __float2bfloat16_rn(v.x - __bfloat162float(h0));
    __nv_bfloat16 l1 = __float2bfloat16_rn(v.y - __bfloat162float(h1));
    __nv_bfloat16 l2 = __float2bfloat16_rn(v.z - __bfloat162float(h2));
    __nv_bfloat16 l3 = __float2bfloat16_rn(v.w - __bfloat162float(h3));
    __nv_bfloat162* ph = reinterpret_cast<__nv_bfloat162*>(g_xhi + i);
    __nv_bfloat162* pl = reinterpret_cast<__nv_bfloat162*>(g_xlo + i);
    ph[0] = __halves2bfloat162(h0, h1); ph[1] = __halves2bfloat162(h2, h3);
    pl[0] = __halves2bfloat162(l0, l1); pl[1] = __halves2bfloat162(l2, l3);
}

// ---------------------------------------------------------------------------
// Prep: kernels [m][d][u] fp32 -> transposed bf16 hi/lo [m][u][d]
// ---------------------------------------------------------------------------
__global__ __launch_bounds__(256) void conv_w(const float* __restrict__ k) {
    __shared__ float t[32][33];
    int m = blockIdx.z, d0 = blockIdx.x * 32, u0 = blockIdx.y * 32;
    int tx = threadIdx.x, ty = threadIdx.y;
    const float* src = k + (size_t)m * D_SZ * U_SZ;
#pragma unroll
    for (int j = 0; j < 4; j++)
        t[ty + 8 * j][tx] = src[(size_t)(d0 + ty + 8 * j) * U_SZ + u0 + tx];
    __syncthreads();
    size_t ob = (size_t)m * U_SZ * D_SZ;
#pragma unroll
    for (int j = 0; j < 4; j++) {
        float v = t[tx][ty + 8 * j];
        __nv_bfloat16 hi = __float2bfloat16_rn(v);
        __nv_bfloat16 lo = __float2bfloat16_rn(v - __bfloat162float(hi));
        size_t oi = ob + (size_t)(u0 + ty + 8 * j) * D_SZ + d0 + tx;
        g_whi[oi] = hi;
        g_wlo[oi] = lo;
    }
}

// ---------------------------------------------------------------------------
// sim kernel (verified R1) — stores sim/16
// ---------------------------------------------------------------------------
__global__ __launch_bounds__(128) void sim_kernel(
    const float* __restrict__ x, const float* __restrict__ key_kernel,
    const float* __restrict__ key_bias, const float* __restrict__ keys_map)
{
    __shared__ float xs[16 * D_SZ];
    __shared__ float kv[16][64];
    int tid = threadIdx.x;
    int b0 = blockIdx.x * 16;
    for (int i = tid; i < 16 * D_SZ; i += 128) xs[i] = x[b0 * D_SZ + i];
    __syncthreads();
    int k = tid & 63, rg = tid >> 6;
    float acc[8];
#pragma unroll
    for (int r = 0; r < 8; r++) acc[r] = 0.f;
    for (int d = 0; d < D_SZ; d++) {
        float kkv = key_kernel[d * 64 + k];
#pragma unroll
        for (int r = 0; r < 8; r++) acc[r] += xs[(rg + 2 * r) * D_SZ + d] * kkv;
    }
    float kb = key_bias[k];
#pragma unroll
    for (int r = 0; r < 8; r++) kv[rg + 2 * r][k] = acc[r] + kb;
    __syncthreads();
    int r = tid >> 3, m0 = tid & 7;
#pragma unroll
    for (int h = 0; h < 2; h++) {
        int m = m0 + h * 8;
        float d2 = 0.f;
#pragma unroll 8
        for (int kk = 0; kk < 64; kk++) {
            float diff = kv[r][kk] - keys_map[m * 64 + kk];
            d2 += diff * diff;
        }
        g_sim[(b0 + r) * M_SZ + m] = 1.0f / (16.0f * (sqrtf(d2) + 1.0f));
    }
}

// ---------------------------------------------------------------------------
// Main HMMA GEMM. 128x128 tile, BK=32, 3-term bf16 hi/lo, 3-stage cp.async,
// mode fold every 16 chunks (sim applied to fp32 partials in registers).
// ---------------------------------------------------------------------------
#define ROWB 80          // padded smem row stride (bytes) for 32 bf16 cols
#define TILEB (128 * ROWB)
#define STAGEB (4 * TILEB)          // Ahi | Alo | Bhi | Blo
#define SM_BIAS (3 * STAGEB)        // 122880
#define SM_SIM  (SM_BIAS + 16 * 128 * 4)
#define SMEM_TOTAL (SM_SIM + 128 * 16 * 4)   // 139264

__device__ __forceinline__ void issue_loads(
    uint32_t st, int brow0, int bcol0, int m, int d0, int tid)
{
#pragma unroll
    for (int j = 0; j < 8; j++) {
        int tile = j >> 1;
        int idx = ((j & 1) << 8) + tid;
        int row = idx >> 2, seg = idx & 3;
        uint32_t saddr = st + tile * TILEB + row * ROWB + seg * 16;
        const __nv_bfloat16* g;
        if (tile == 0)
            g = g_xhi + (size_t)(brow0 + row) * D_SZ + d0 + seg * 8;
        else if (tile == 1)
            g = g_xlo + (size_t)(brow0 + row) * D_SZ + d0 + seg * 8;
        else if (tile == 2)
            g = g_whi + ((size_t)m * U_SZ + bcol0 + row) * D_SZ + d0 + seg * 8;
        else
            g = g_wlo + ((size_t)m * U_SZ + bcol0 + row) * D_SZ + d0 + seg * 8;
        cp_async16(saddr, g);
    }
}

__global__ __launch_bounds__(256, 1) void pd_mma(
    const float* __restrict__ biases, float* __restrict__ out)
{
    extern __shared__ __align__(1024) char smem[];
    uint32_t sb = smem_u32(smem);
    int tid = threadIdx.x;
    int lane = tid & 31, warp = tid >> 5;
    int wm = warp & 3, wn = warp >> 2;     // 4 x 2 warp grid
    int brow0 = blockIdx.y * 128;
    int bcol0 = blockIdx.x * 128;

    float* bias_sm = reinterpret_cast<float*>(smem + SM_BIAS);   // [16][128]
    float* sim_sm  = reinterpret_cast<float*>(smem + SM_SIM);    // [128][16]
    for (int i = tid; i < 16 * 128; i += 256)
        bias_sm[i] = biases[(i >> 7) * U_SZ + bcol0 + (i & 127)];
    for (int i = tid; i < 128 * 16; i += 256)
        sim_sm[i] = g_sim[(brow0 + (i >> 4)) * M_SZ + (i & 15)];
    __syncthreads();

    // ldmatrix smem offsets (relative to stage base)
    uint32_t aoff[2], boff[8];
#pragma unroll
    for (int mt = 0; mt < 2; mt++)
        aoff[mt] = (uint32_t)((wm * 32 + mt * 16 + (lane & 15)) * ROWB +
                              ((lane >> 4) * 16));
#pragma unroll
    for (int nt = 0; nt < 8; nt++)
        boff[nt] = (uint32_t)(2 * TILEB +
                              (wn * 64 + nt * 8 + (lane & 7)) * ROWB +
                              (((lane >> 3) & 1) * 16));

    float macc[2][8][4], facc[2][8][4];
#pragma unroll
    for (int mt = 0; mt < 2; mt++)
#pragma unroll
        for (int nt = 0; nt < 8; nt++)
#pragma unroll
            for (int i = 0; i < 4; i++) { macc[mt][nt][i] = 0.f; facc[mt][nt][i] = 0.f; }

    // prologue: stages 0,1
    issue_loads(sb, brow0, bcol0, 0, 0, tid);
    asm volatile("cp.async.commit_group;" ::: "memory");
    issue_loads(sb + STAGEB, brow0, bcol0, 0, 32, tid);
    asm volatile("cp.async.commit_group;" ::: "memory");

    for (int it = 0; it < 256; it++) {
        __syncthreads();       // all warps done reading stage (it+2)%3
        int it2 = it + 2;
        if (it2 < 256)
            issue_loads(sb + (it2 % 3) * STAGEB, brow0, bcol0,
                        it2 >> 4, (it2 & 15) * 32, tid);
        asm volatile("cp.async.commit_group;" ::: "memory");
        asm volatile("cp.async.wait_group 2;" ::: "memory");
        __syncthreads();       // stage it%3 visible to all warps

        uint32_t st = sb + (it % 3) * STAGEB;
#pragma unroll
        for (int ks = 0; ks < 2; ks++) {
            uint32_t ah[2][4], al[2][4], bh[8][2], bl[8][2];
#pragma unroll
            for (int mt = 0; mt < 2; mt++) {
                ldsm4(ah[mt], st + aoff[mt] + ks * 32);
                ldsm4(al[mt], st + TILEB + aoff[mt] + ks * 32);
            }
#pragma unroll
            for (int nt = 0; nt < 8; nt++) {
                ldsm2(bh[nt], st + boff[nt] + ks * 32);
                ldsm2(bl[nt], st + TILEB + boff[nt] + ks * 32);
            }
            // term 1: Ahi * Bhi
#pragma unroll
            for (int mt = 0; mt < 2; mt++)
#pragma unroll
                for (int nt = 0; nt < 8; nt++)
                    mma16816(macc[mt][nt], ah[mt], bh[nt]);
            // term 2: Ahi * Blo
#pragma unroll
            for (int mt = 0; mt < 2; mt++)
#pragma unroll
                for (int nt = 0; nt < 8; nt++)
                    mma16816(macc[mt][nt], ah[mt], bl[nt]);
            // term 3: Alo * Bhi
#pragma unroll
            for (int mt = 0; mt < 2; mt++)
#pragma unroll
                for (int nt = 0; nt < 8; nt++)
                    mma16816(macc[mt][nt], al[mt], bh[nt]);
        }

        if ((it & 15) == 15) {        // mode boundary: fold partials
            int m = it >> 4;
#pragma unroll
            for (int mt = 0; mt < 2; mt++) {
                int ra = wm * 32 + mt * 16 + (lane >> 2);
                float sa = sim_sm[ra * 16 + m];
                float sb_ = sim_sm[(ra + 8) * 16 + m];
#pragma unroll
                for (int nt = 0; nt < 8; nt++) {
                    facc[mt][nt][0] += sa  * macc[mt][nt][0];
                    facc[mt][nt][1] += sa  * macc[mt][nt][1];
                    facc[mt][nt][2] += sb_ * macc[mt][nt][2];
                    facc[mt][nt][3] += sb_ * macc[mt][nt][3];
                    macc[mt][nt][0] = 0.f; macc[mt][nt][1] = 0.f;
                    macc[mt][nt][2] = 0.f; macc[mt][nt][3] = 0.f;
                }
            }
        }
    }

    // bias fold:  facc += sum_m (sim/16)[row,m] * biases[m,col]
#pragma unroll
    for (int mt = 0; mt < 2; mt++) {
        int ra = wm * 32 + mt * 16 + (lane >> 2);
        for (int m = 0; m < 16; m++) {
            float sa = sim_sm[ra * 16 + m];
            float sb_ = sim_sm[(ra + 8) * 16 + m];
#pragma unroll
            for (int nt = 0; nt < 8; nt++) {
                int col = wn * 64 + nt * 8 + 2 * (lane & 3);
                float b0 = bias_sm[m * 128 + col];
                float b1 = bias_sm[m * 128 + col + 1];
                facc[mt][nt][0] += sa * b0;  facc[mt][nt][1] += sa * b1;
                facc[mt][nt][2] += sb_ * b0; facc[mt][nt][3] += sb_ * b1;
            }
        }
    }

    // store
#pragma unroll
    for (int mt = 0; mt < 2; mt++) {
        int ra = brow0 + wm * 32 + mt * 16 + (lane >> 2);
#pragma unroll
        for (int nt = 0; nt < 8; nt++) {
            int col = bcol0 + wn * 64 + nt * 8 + 2 * (lane & 3);
            *reinterpret_cast<float2*>(&out[(size_t)ra * U_SZ + col]) =
                make_float2(facc[mt][nt][0], facc[mt][nt][1]);
            *reinterpret_cast<float2*>(&out[(size_t)(ra + 8) * U_SZ + col]) =
                make_float2(facc[mt][nt][2], facc[mt][nt][3]);
        }
    }
}

// ---------------------------------------------------------------------------
extern "C" void kernel_launch(void* const* d_in, const int* in_sizes, int n_in,
                              void* d_out, int out_size)
{
    const float* x          = (const float*)d_in[0];
    const float* key_kernel = (const float*)d_in[1];
    const float* key_bias   = (const float*)d_in[2];
    const float* keys_map   = (const float*)d_in[3];
    const float* kernels    = (const float*)d_in[4];
    const float* biases     = (const float*)d_in[5];
    float* out = (float*)d_out;

    cudaFuncSetAttribute(pd_mma, cudaFuncAttributeMaxDynamicSharedMemorySize,
                         SMEM_TOTAL);

    conv_x<<<(B_SZ * D_SZ) / (256 * 4), 256>>>(x);
    conv_w<<<dim3(16, 16, 16), dim3(32, 8)>>>(kernels);
    sim_kernel<<<B_SZ / 16, 128>>>(x, key_kernel, key_bias, keys_map);

    dim3 grid(U_SZ / 128, B_SZ / 128);
    pd_mma<<<grid, 256, SMEM_TOTAL>>>(biases, out);
}

// round 4
// speedup vs baseline: 1.9330x; 1.0170x over previous
#include <cuda_runtime.h>
#include <cuda_bf16.h>
#include <cstdint>

#define B_SZ 8192
#define D_SZ 512
#define U_SZ 512
#define M_SZ 16

// ---------------------------------------------------------------------------
// Scratch (static __device__ — no allocations allowed)
// ---------------------------------------------------------------------------
__device__ float         g_sim[B_SZ * M_SZ];          // sim/16
__device__ __nv_bfloat16 g_xhi[B_SZ * D_SZ];
__device__ __nv_bfloat16 g_xlo[B_SZ * D_SZ];
__device__ __nv_bfloat16 g_whi[M_SZ * U_SZ * D_SZ];   // [m][u][d]  (k-major B)
__device__ __nv_bfloat16 g_wlo[M_SZ * U_SZ * D_SZ];

// ---------------------------------------------------------------------------
// helpers
// ---------------------------------------------------------------------------
__device__ __forceinline__ uint32_t smem_u32(const void* p) {
    uint32_t a;
    asm("{ .reg .u64 t; cvta.to.shared.u64 t, %1; cvt.u32.u64 %0, t; }"
        : "=r"(a) : "l"(p));
    return a;
}
__device__ __forceinline__ void cp_async16(uint32_t saddr, const void* gaddr) {
    asm volatile("cp.async.cg.shared.global [%0], [%1], 16;"
                 :: "r"(saddr), "l"(gaddr) : "memory");
}
__device__ __forceinline__ void ldsm4(uint32_t* r, uint32_t a) {
    asm volatile("ldmatrix.sync.aligned.m8n8.x4.shared.b16 {%0,%1,%2,%3}, [%4];"
                 : "=r"(r[0]), "=r"(r[1]), "=r"(r[2]), "=r"(r[3]) : "r"(a));
}
__device__ __forceinline__ void mma16816(float* c, const uint32_t* a, const uint32_t* b) {
    asm volatile(
        "mma.sync.aligned.m16n8k16.row.col.f32.bf16.bf16.f32 "
        "{%0,%1,%2,%3}, {%4,%5,%6,%7}, {%8,%9}, {%0,%1,%2,%3};"
        : "+f"(c[0]), "+f"(c[1]), "+f"(c[2]), "+f"(c[3])
        : "r"(a[0]), "r"(a[1]), "r"(a[2]), "r"(a[3]), "r"(b[0]), "r"(b[1]));
}

// ---------------------------------------------------------------------------
// Prep: fp32 -> bf16 hi/lo split of x
// ---------------------------------------------------------------------------
__global__ __launch_bounds__(256) void conv_x(const float* __restrict__ x) {
    size_t i = ((size_t)blockIdx.x * 256 + threadIdx.x) * 4;
    float4 v = *reinterpret_cast<const float4*>(x + i);
    __nv_bfloat16 h0 = __float2bfloat16_rn(v.x), h1 = __float2bfloat16_rn(v.y);
    __nv_bfloat16 h2 = __float2bfloat16_rn(v.z), h3 = __float2bfloat16_rn(v.w);
    __nv_bfloat16 l0 = __float2bfloat16_rn(v.x - __bfloat162float(h0));
    __nv_bfloat16 l1 = __float2bfloat16_rn(v.y - __bfloat162float(h1));
    __nv_bfloat16 l2 = __float2bfloat16_rn(v.z - __bfloat162float(h2));
    __nv_bfloat16 l3 = __float2bfloat16_rn(v.w - __bfloat162float(h3));
    __nv_bfloat162* ph = reinterpret_cast<__nv_bfloat162*>(g_xhi + i);
    __nv_bfloat162* pl = reinterpret_cast<__nv_bfloat162*>(g_xlo + i);
    ph[0] = __halves2bfloat162(h0, h1); ph[1] = __halves2bfloat162(h2, h3);
    pl[0] = __halves2bfloat162(l0, l1); pl[1] = __halves2bfloat162(l2, l3);
}

// ---------------------------------------------------------------------------
// Prep: kernels [m][d][u] fp32 -> transposed bf16 hi/lo [m][u][d]
// ---------------------------------------------------------------------------
__global__ __launch_bounds__(256) void conv_w(const float* __restrict__ k) {
    __shared__ float t[32][33];
    int m = blockIdx.z, d0 = blockIdx.x * 32, u0 = blockIdx.y * 32;
    int tx = threadIdx.x, ty = threadIdx.y;
    const float* src = k + (size_t)m * D_SZ * U_SZ;
#pragma unroll
    for (int j = 0; j < 4; j++)
        t[ty + 8 * j][tx] = src[(size_t)(d0 + ty + 8 * j) * U_SZ + u0 + tx];
    __syncthreads();
    size_t ob = (size_t)m * U_SZ * D_SZ;
#pragma unroll
    for (int j = 0; j < 4; j++) {
        float v = t[tx][ty + 8 * j];
        __nv_bfloat16 hi = __float2bfloat16_rn(v);
        __nv_bfloat16 lo = __float2bfloat16_rn(v - __bfloat162float(hi));
        size_t oi = ob + (size_t)(u0 + ty + 8 * j) * D_SZ + d0 + tx;
        g_whi[oi] = hi;
        g_wlo[oi] = lo;
    }
}

// ---------------------------------------------------------------------------
// sim kernel (verified R1) — stores sim/16
// ---------------------------------------------------------------------------
__global__ __launch_bounds__(128) void sim_kernel(
    const float* __restrict__ x, const float* __restrict__ key_kernel,
    const float* __restrict__ key_bias, const float* __restrict__ keys_map)
{
    __shared__ float xs[16 * D_SZ];
    __shared__ float kv[16][64];
    int tid = threadIdx.x;
    int b0 = blockIdx.x * 16;
    for (int i = tid; i < 16 * D_SZ; i += 128) xs[i] = x[b0 * D_SZ + i];
    __syncthreads();
    int k = tid & 63, rg = tid >> 6;
    float acc[8];
#pragma unroll
    for (int r = 0; r < 8; r++) acc[r] = 0.f;
    for (int d = 0; d < D_SZ; d++) {
        float kkv = key_kernel[d * 64 + k];
#pragma unroll
        for (int r = 0; r < 8; r++) acc[r] += xs[(rg + 2 * r) * D_SZ + d] * kkv;
    }
    float kb = key_bias[k];
#pragma unroll
    for (int r = 0; r < 8; r++) kv[rg + 2 * r][k] = acc[r] + kb;
    __syncthreads();
    int r = tid >> 3, m0 = tid & 7;
#pragma unroll
    for (int h = 0; h < 2; h++) {
        int m = m0 + h * 8;
        float d2 = 0.f;
#pragma unroll 8
        for (int kk = 0; kk < 64; kk++) {
            float diff = kv[r][kk] - keys_map[m * 64 + kk];
            d2 += diff * diff;
        }
        g_sim[(b0 + r) * M_SZ + m] = 1.0f / (16.0f * (sqrtf(d2) + 1.0f));
    }
}

// ---------------------------------------------------------------------------
// Main HMMA GEMM. 128x128 tile, BK=32, 3-term bf16 hi/lo, 3-stage cp.async,
// 16 warps (4x4 grid, warp tile 32x32), ONE barrier per iteration,
// mode fold every 16 chunks (sim applied to fp32 partials in registers).
// ---------------------------------------------------------------------------
#define ROWB 80          // padded smem row stride (bytes) for 32 bf16 cols
#define TILEB (128 * ROWB)
#define STAGEB (4 * TILEB)          // Ahi | Alo | Bhi | Blo
#define SM_BIAS (3 * STAGEB)        // 122880
#define SM_SIM  (SM_BIAS + 16 * 128 * 4)
#define SMEM_TOTAL (SM_SIM + 128 * 16 * 4)   // 139264

__device__ __forceinline__ void issue_loads(
    uint32_t st, int brow0, int bcol0, int m, int d0, int tid)
{
    int row = tid >> 2, seg = tid & 3;           // 512 threads: 1 cp16 per tile
    uint32_t so = (uint32_t)(row * ROWB + seg * 16);
    cp_async16(st + so,
               g_xhi + (size_t)(brow0 + row) * D_SZ + d0 + seg * 8);
    cp_async16(st + TILEB + so,
               g_xlo + (size_t)(brow0 + row) * D_SZ + d0 + seg * 8);
    cp_async16(st + 2 * TILEB + so,
               g_whi + ((size_t)m * U_SZ + bcol0 + row) * D_SZ + d0 + seg * 8);
    cp_async16(st + 3 * TILEB + so,
               g_wlo + ((size_t)m * U_SZ + bcol0 + row) * D_SZ + d0 + seg * 8);
}

__global__ __launch_bounds__(512, 1) void pd_mma(
    const float* __restrict__ biases, float* __restrict__ out)
{
    extern __shared__ __align__(1024) char smem[];
    uint32_t sb = smem_u32(smem);
    int tid = threadIdx.x;
    int lane = tid & 31, warp = tid >> 5;
    int wm = warp & 3, wn = warp >> 2;     // 4 x 4 warp grid
    int brow0 = blockIdx.y * 128;
    int bcol0 = blockIdx.x * 128;

    float* bias_sm = reinterpret_cast<float*>(smem + SM_BIAS);   // [16][128]
    float* sim_sm  = reinterpret_cast<float*>(smem + SM_SIM);    // [128][16]
    for (int i = tid; i < 16 * 128; i += 512)
        bias_sm[i] = biases[(i >> 7) * U_SZ + bcol0 + (i & 127)];
    for (int i = tid; i < 128 * 16; i += 512)
        sim_sm[i] = g_sim[(brow0 + (i >> 4)) * M_SZ + (i & 15)];

    // ldmatrix smem offsets (relative to stage/tile base)
    uint32_t aoff[2], boff[2];
#pragma unroll
    for (int mt = 0; mt < 2; mt++)
        aoff[mt] = (uint32_t)((wm * 32 + mt * 16 + (lane & 15)) * ROWB +
                              ((lane >> 4) * 16));
#pragma unroll
    for (int p = 0; p < 2; p++)
        boff[p] = (uint32_t)((wn * 32 + p * 16 + ((lane >> 4) * 8) + (lane & 7)) * ROWB +
                             (((lane >> 3) & 1) * 16));

    float macc[2][4][4], facc[2][4][4];
#pragma unroll
    for (int mt = 0; mt < 2; mt++)
#pragma unroll
        for (int nt = 0; nt < 4; nt++)
#pragma unroll
            for (int i = 0; i < 4; i++) { macc[mt][nt][i] = 0.f; facc[mt][nt][i] = 0.f; }

    // prologue: stages 0,1
    issue_loads(sb, brow0, bcol0, 0, 0, tid);
    asm volatile("cp.async.commit_group;" ::: "memory");
    issue_loads(sb + STAGEB, brow0, bcol0, 0, 32, tid);
    asm volatile("cp.async.commit_group;" ::: "memory");

    for (int it = 0; it < 256; it++) {
        // group `it` complete (in-order completion; committed so far: 0..it+1)
        asm volatile("cp.async.wait_group 1;" ::: "memory");
        // visibility of group `it` across threads + all warps finished
        // reading stage (it-1)%3 (ldsm are synchronous register loads)
        __syncthreads();
        int it2 = it + 2;
        if (it2 < 256)
            issue_loads(sb + (it2 % 3) * STAGEB, brow0, bcol0,
                        it2 >> 4, (it2 & 15) * 32, tid);
        asm volatile("cp.async.commit_group;" ::: "memory");

        uint32_t st = sb + (it % 3) * STAGEB;
#pragma unroll
        for (int ks = 0; ks < 2; ks++) {
            uint32_t ah[2][4], al[2][4], bh[2][4], bl[2][4];
#pragma unroll
            for (int mt = 0; mt < 2; mt++) {
                ldsm4(ah[mt], st + aoff[mt] + ks * 32);
                ldsm4(al[mt], st + TILEB + aoff[mt] + ks * 32);
            }
#pragma unroll
            for (int p = 0; p < 2; p++) {
                ldsm4(bh[p], st + 2 * TILEB + boff[p] + ks * 32);
                ldsm4(bl[p], st + 3 * TILEB + boff[p] + ks * 32);
            }
            // term 1: Ahi * Bhi
#pragma unroll
            for (int mt = 0; mt < 2; mt++)
#pragma unroll
                for (int p = 0; p < 2; p++) {
                    mma16816(macc[mt][2 * p],     ah[mt], &bh[p][0]);
                    mma16816(macc[mt][2 * p + 1], ah[mt], &bh[p][2]);
                }
            // term 2: Ahi * Blo
#pragma unroll
            for (int mt = 0; mt < 2; mt++)
#pragma unroll
                for (int p = 0; p < 2; p++) {
                    mma16816(macc[mt][2 * p],     ah[mt], &bl[p][0]);
                    mma16816(macc[mt][2 * p + 1], ah[mt], &bl[p][2]);
                }
            // term 3: Alo * Bhi
#pragma unroll
            for (int mt = 0; mt < 2; mt++)
#pragma unroll
                for (int p = 0; p < 2; p++) {
                    mma16816(macc[mt][2 * p],     al[mt], &bh[p][0]);
                    mma16816(macc[mt][2 * p + 1], al[mt], &bh[p][2]);
                }
        }

        if ((it & 15) == 15) {        // mode boundary: fold partials
            int m = it >> 4;
#pragma unroll
            for (int mt = 0; mt < 2; mt++) {
                int ra = wm * 32 + mt * 16 + (lane >> 2);
                float sa = sim_sm[ra * 16 + m];
                float sb_ = sim_sm[(ra + 8) * 16 + m];
#pragma unroll
                for (int nt = 0; nt < 4; nt++) {
                    facc[mt][nt][0] += sa  * macc[mt][nt][0];
                    facc[mt][nt][1] += sa  * macc[mt][nt][1];
                    facc[mt][nt][2] += sb_ * macc[mt][nt][2];
                    facc[mt][nt][3] += sb_ * macc[mt][nt][3];
                    macc[mt][nt][0] = 0.f; macc[mt][nt][1] = 0.f;
                    macc[mt][nt][2] = 0.f; macc[mt][nt][3] = 0.f;
                }
            }
        }
    }

    // bias fold:  facc += sum_m (sim/16)[row,m] * biases[m,col]
#pragma unroll
    for (int mt = 0; mt < 2; mt++) {
        int ra = wm * 32 + mt * 16 + (lane >> 2);
        for (int m = 0; m < 16; m++) {
            float sa = sim_sm[ra * 16 + m];
            float sb_ = sim_sm[(ra + 8) * 16 + m];
#pragma unroll
            for (int nt = 0; nt < 4; nt++) {
                int col = wn * 32 + nt * 8 + 2 * (lane & 3);
                float b0 = bias_sm[m * 128 + col];
                float b1 = bias_sm[m * 128 + col + 1];
                facc[mt][nt][0] += sa * b0;  facc[mt][nt][1] += sa * b1;
                facc[mt][nt][2] += sb_ * b0; facc[mt][nt][3] += sb_ * b1;
            }
        }
    }

    // store
#pragma unroll
    for (int mt = 0; mt < 2; mt++) {
        int ra = brow0 + wm * 32 + mt * 16 + (lane >> 2);
#pragma unroll
        for (int nt = 0; nt < 4; nt++) {
            int col = bcol0 + wn * 32 + nt * 8 + 2 * (lane & 3);
            *reinterpret_cast<float2*>(&out[(size_t)ra * U_SZ + col]) =
                make_float2(facc[mt][nt][0], facc[mt][nt][1]);
            *reinterpret_cast<float2*>(&out[(size_t)(ra + 8) * U_SZ + col]) =
                make_float2(facc[mt][nt][2], facc[mt][nt][3]);
        }
    }
}

// ---------------------------------------------------------------------------
extern "C" void kernel_launch(void* const* d_in, const int* in_sizes, int n_in,
                              void* d_out, int out_size)
{
    const float* x          = (const float*)d_in[0];
    const float* key_kernel = (const float*)d_in[1];
    const float* key_bias   = (const float*)d_in[2];
    const float* keys_map   = (const float*)d_in[3];
    const float* kernels    = (const float*)d_in[4];
    const float* biases     = (const float*)d_in[5];
    float* out = (float*)d_out;

    cudaFuncSetAttribute(pd_mma, cudaFuncAttributeMaxDynamicSharedMemorySize,
                         SMEM_TOTAL);

    conv_x<<<(B_SZ * D_SZ) / (256 * 4), 256>>>(x);
    conv_w<<<dim3(16, 16, 16), dim3(32, 8)>>>(kernels);
    sim_kernel<<<B_SZ / 16, 128>>>(x, key_kernel, key_bias, keys_map);

    dim3 grid(U_SZ / 128, B_SZ / 128);
    pd_mma<<<grid, 512, SMEM_TOTAL>>>(biases, out);
}